// round 11
// baseline (speedup 1.0000x reference)
#include <cuda_runtime.h>

// Problem constants (fixed by the reference: x=(128,128,16,16) f32, logits=(128,100))
#define B_  128
#define D_  32768            // C*H*W
#define D4_ (D_/4)           // 8192 float4 per prototype row
#define K_  100
#define TJ_ 10               // j-tile width (register-resident pj)
#define NCHUNK_ 32           // d4 chunks of 256
#define NGROUP_ (NCHUNK_ * (K_ / TJ_))   // 320 groups = (d4 chunk, j-tile)
#define UNITS_  (NGROUP_ * K_)           // 32000 units = group x i-class
#define NB_     592                      // persistent blocks = 148 SM x 4
#define BASE_   (UNITS_ / NB_)           // 54
#define REM_    (UNITS_ % NB_)           // 32

// Scratch (allocation-free rule: __device__ globals)
__device__ int   g_items[B_];    // CSR items: batch indices grouped by class, ascending
__device__ int   g_off[K_ + 1];  // CSR offsets
__device__ float g_inv[K_];      // 1/count (0 if count==0)

// ---------------------------------------------------------------------------
// Kernel 1: argmax per batch row + deterministic CSR build (single block).
// 1024 threads, 8 per row -> high MLP on the 51 KB logits read.
// softmax monotone -> argmax(probs) == argmax(logits); strict > + ascending
// scan + (value,index) shuffle reduce matches jnp.argmax tie-breaking.
// CSR: counts via smem atomics, serial smem prefix, stable rank scan ->
// bitwise-deterministic. PDL trigger at the end.
// ---------------------------------------------------------------------------
__global__ __launch_bounds__(1024) void argmax_csr_kernel(
        const float* __restrict__ logits) {
    __shared__ int s_cls[B_];
    __shared__ int s_cnt[K_];
    __shared__ int s_off[K_ + 1];

    int tid = threadIdx.x;        // 0..1023
    int b   = tid >> 3;           // row 0..127
    int sub = tid & 7;            // 0..7 within row

    if (tid < K_) s_cnt[tid] = 0;

    const float* row = logits + (size_t)b * K_;
    float v   = row[sub];
    int   idx = sub;
    #pragma unroll
    for (int k = sub + 8; k < K_; k += 8) {
        float t = row[k];
        if (t > v) { v = t; idx = k; }   // ascending + strict > => lowest index kept
    }
    #pragma unroll
    for (int off = 4; off > 0; off >>= 1) {
        float ov = __shfl_down_sync(0xffffffffu, v,   off, 8);
        int   oi = __shfl_down_sync(0xffffffffu, idx, off, 8);
        if (ov > v || (ov == v && oi < idx)) { v = ov; idx = oi; }
    }
    __syncthreads();              // counts zeroed before atomics
    if (sub == 0) {
        s_cls[b] = idx;
        atomicAdd(&s_cnt[idx], 1);
    }
    __syncthreads();

    if (tid == 0) {
        int off = 0;
        #pragma unroll 4
        for (int k = 0; k < K_; k++) { s_off[k] = off; off += s_cnt[k]; }
        s_off[K_] = off;
    }
    __syncthreads();

    if (tid < B_) {
        int myc = s_cls[tid];
        int rank = 0;
        #pragma unroll 8
        for (int bb = 0; bb < B_; bb++)
            rank += (bb < tid && s_cls[bb] == myc) ? 1 : 0;
        g_items[s_off[myc] + rank] = tid;
    }

    if (tid < K_) {
        g_off[tid] = s_off[tid];
        int c = s_cnt[tid];
        g_inv[tid] = (c > 0) ? (1.0f / (float)c) : 0.0f;
    }
    if (tid == 0) g_off[K_] = s_off[K_];

    cudaTriggerProgrammaticLaunchCompletion();
}

// ---------------------------------------------------------------------------
// Kernel 2 (persistent, fused): prototypes + inter-class matrix.
// 32000 uniform work units: unit = (group, i-class); group = (d4 chunk,
// j-tile of 10 classes). Exactly 592 blocks (148 SM x 4, forced by
// __launch_bounds__(256,4)); block b owns a CONTIGUOUS 54/55-unit range
// (i innermost) -> crosses at most one group boundary -> pj[10] recomputed
// at most twice per block. Tail quantization: 55/54.05 = +1.75% vs the old
// 10x10 tiling's +11% (6 waves vs 5.405).
// NO dynamic register indexing anywhere (the R9/R10 trap that spilled pj to
// local memory): pj only indexed by unrolled constants; pi is always
// recomputed from the CSR (L2-hit reads), including on diagonal rows.
// Accumulation strictly in CSR order -> bitwise-identical everywhere.
// Proto output written by the block that processes unit i==0 of each group
// with j-ownership d4-chunk pass (each group start processed exactly once).
// __stcs on all output: the 1.33 GB write stream is never re-read.
// ---------------------------------------------------------------------------
__global__ __launch_bounds__(256, 4) void inter_fused_kernel(
        const float4* __restrict__ x4,
        float4* __restrict__ proto4,
        float4* __restrict__ out4) {
    __shared__ int   s_off[K_ + 1];
    __shared__ int   s_items[B_];
    __shared__ float s_inv[K_];

    // Wait for argmax_csr_kernel's g_* publishes (PDL dependency).
    cudaGridDependencySynchronize();

    const int t = threadIdx.x;
    if (t < K_ + 1) s_off[t]   = g_off[t];
    if (t < B_)     s_items[t] = g_items[t];
    if (t < K_)     s_inv[t]   = g_inv[t];
    __syncthreads();

    // balanced contiguous partition: first REM_ blocks get BASE_+1 units
    const int b     = blockIdx.x;
    const int extra = (b < REM_) ? b : REM_;
    const int u0    = b * BASE_ + extra;
    const int cnt   = BASE_ + (b < REM_ ? 1 : 0);

    int grp = u0 / K_;            // group 0..319
    int i   = u0 - grp * K_;      // i-class 0..99

    int d4  = (grp % NCHUNK_) * 256 + t;     // float4 column
    int j0  = (grp / NCHUNK_) * TJ_;         // j-tile base class

    // compute pj for the current group
    float4 pj[TJ_];
    #pragma unroll
    for (int jj = 0; jj < TJ_; jj++) {
        const int k = j0 + jj;
        float4 acc = make_float4(0.f, 0.f, 0.f, 0.f);
        const int s = s_off[k], e = s_off[k + 1];
        for (int u = s; u < e; u++) {
            float4 v = x4[(size_t)s_items[u] * D4_ + d4];
            acc.x += v.x; acc.y += v.y; acc.z += v.z; acc.w += v.w;
        }
        const float inv = s_inv[k];  // count==0 -> acc==0, inv==0 -> 0 (matches where())
        acc.x *= inv; acc.y *= inv; acc.z *= inv; acc.w *= inv;
        pj[jj] = acc;
    }

    for (int n = 0; n < cnt; n++) {
        // proto output: the processor of unit i==0 of each group owns the
        // group's proto rows, but only groups in d4-chunk pass (grp%32) cover
        // distinct d4 -- every (j-row, d4) pair is hit exactly once overall.
        if (i == 0) {
            #pragma unroll
            for (int jj = 0; jj < TJ_; jj++)
                __stcs(&proto4[(size_t)(j0 + jj) * D4_ + d4], pj[jj]);
        }

        // pi for class i (always recomputed; CSR order -> deterministic)
        float4 pi;
        {
            float4 acc = make_float4(0.f, 0.f, 0.f, 0.f);
            const int s = s_off[i], e = s_off[i + 1];
            for (int u = s; u < e; u++) {
                float4 v = x4[(size_t)s_items[u] * D4_ + d4];
                acc.x += v.x; acc.y += v.y; acc.z += v.z; acc.w += v.w;
            }
            const float inv = s_inv[i];
            acc.x *= inv; acc.y *= inv; acc.z *= inv; acc.w *= inv;
            pi = acc;
        }

        #pragma unroll
        for (int jj = 0; jj < TJ_; jj++) {
            float4 r;
            r.x = pj[jj].x - pi.x;
            r.y = pj[jj].y - pi.y;
            r.z = pj[jj].z - pi.z;
            r.w = pj[jj].w - pi.w;
            __stcs(&out4[(size_t)(i * K_ + (j0 + jj)) * D4_ + d4], r);
        }

        // advance unit; on group change, recompute pj (at most once per block)
        if (++i == K_) {
            i = 0;
            grp++;
            if (n + 1 < cnt) {
                d4 = (grp % NCHUNK_) * 256 + t;
                j0 = (grp / NCHUNK_) * TJ_;
                #pragma unroll
                for (int jj = 0; jj < TJ_; jj++) {
                    const int k = j0 + jj;
                    float4 acc = make_float4(0.f, 0.f, 0.f, 0.f);
                    const int s = s_off[k], e = s_off[k + 1];
                    for (int u = s; u < e; u++) {
                        float4 v = x4[(size_t)s_items[u] * D4_ + d4];
                        acc.x += v.x; acc.y += v.y; acc.z += v.z; acc.w += v.w;
                    }
                    const float inv = s_inv[k];
                    acc.x *= inv; acc.y *= inv; acc.z *= inv; acc.w *= inv;
                    pj[jj] = acc;
                }
            }
        }
    }
}

// ---------------------------------------------------------------------------
// Launcher. Output layout: [prototypes (100*32768 f32) | inter (100*100*32768 f32)]
// ---------------------------------------------------------------------------
extern "C" void kernel_launch(void* const* d_in, const int* in_sizes, int n_in,
                              void* d_out, int out_size) {
    const float* x      = (const float*)d_in[0];   // (128,128,16,16) f32
    const float* logits = (const float*)d_in[1];   // (128,100) f32
    float* out = (float*)d_out;

    const float4* x4     = (const float4*)x;
    float4*       proto4 = (float4*)out;                       // first 819200 float4
    float4*       inter4 = (float4*)out + (size_t)K_ * D4_;    // rest

    argmax_csr_kernel<<<1, 1024>>>(logits);

    cudaLaunchConfig_t cfg = {};
    cfg.gridDim  = dim3(NB_);        // 592 persistent blocks = 148 SM x 4
    cfg.blockDim = dim3(256);
    cfg.dynamicSmemBytes = 0;
    cfg.stream = 0;
    cudaLaunchAttribute attrs[1];
    attrs[0].id = cudaLaunchAttributeProgrammaticStreamSerialization;
    attrs[0].val.programmaticStreamSerializationAllowed = 1;
    cfg.attrs = attrs;
    cfg.numAttrs = 1;
    cudaLaunchKernelEx(&cfg, inter_fused_kernel, x4, proto4, inter4);
}

// round 12
// speedup vs baseline: 1.1395x; 1.1395x over previous
#include <cuda_runtime.h>

// Problem constants (fixed by the reference: x=(128,128,16,16) f32, logits=(128,100))
#define B_  128
#define D_  32768          // C*H*W
#define D4_ (D_/4)         // 8192 float4 per prototype row
#define K_  100
#define TILE_ 10           // 10x10 class tile
#define NCHUNK_ 32         // d4 chunks of 256
#define NDIAG_  (NCHUNK_ * TILE_)            // 320 diagonal logical tiles
#define NNOND_  (NCHUNK_ * 90)               // 2880 non-diagonal logical tiles

// Scratch (allocation-free rule: __device__ globals)
__device__ int   g_items[B_];    // CSR items: batch indices grouped by class, ascending
__device__ int   g_off[K_ + 1];  // CSR offsets
__device__ float g_inv[K_];      // 1/count (0 if count==0)

// ---------------------------------------------------------------------------
// Kernel 1: argmax per batch row + deterministic CSR build (single block).
// 1024 threads, 8 per row -> high MLP on the 51 KB logits read.
// softmax monotone -> argmax(probs) == argmax(logits); strict > + ascending
// scan + (value,index) shuffle reduce matches jnp.argmax tie-breaking.
// CSR: counts via smem atomics, serial smem prefix, stable rank scan ->
// bitwise-deterministic. PDL trigger at the end.
// ---------------------------------------------------------------------------
__global__ __launch_bounds__(1024) void argmax_csr_kernel(
        const float* __restrict__ logits) {
    __shared__ int s_cls[B_];
    __shared__ int s_cnt[K_];
    __shared__ int s_off[K_ + 1];

    int tid = threadIdx.x;        // 0..1023
    int b   = tid >> 3;           // row 0..127
    int sub = tid & 7;            // 0..7 within row

    if (tid < K_) s_cnt[tid] = 0;

    const float* row = logits + (size_t)b * K_;
    float v   = row[sub];
    int   idx = sub;
    #pragma unroll
    for (int k = sub + 8; k < K_; k += 8) {
        float t = row[k];
        if (t > v) { v = t; idx = k; }   // ascending + strict > => lowest index kept
    }
    #pragma unroll
    for (int off = 4; off > 0; off >>= 1) {
        float ov = __shfl_down_sync(0xffffffffu, v,   off, 8);
        int   oi = __shfl_down_sync(0xffffffffu, idx, off, 8);
        if (ov > v || (ov == v && oi < idx)) { v = ov; idx = oi; }
    }
    __syncthreads();              // counts zeroed before atomics
    if (sub == 0) {
        s_cls[b] = idx;
        atomicAdd(&s_cnt[idx], 1);
    }
    __syncthreads();

    if (tid == 0) {
        int off = 0;
        #pragma unroll 4
        for (int k = 0; k < K_; k++) { s_off[k] = off; off += s_cnt[k]; }
        s_off[K_] = off;
    }
    __syncthreads();

    if (tid < B_) {
        int myc = s_cls[tid];
        int rank = 0;
        #pragma unroll 8
        for (int bb = 0; bb < B_; bb++)
            rank += (bb < tid && s_cls[bb] == myc) ? 1 : 0;
        g_items[s_off[myc] + rank] = tid;
    }

    if (tid < K_) {
        g_off[tid] = s_off[tid];
        int c = s_cnt[tid];
        g_inv[tid] = (c > 0) ? (1.0f / (float)c) : 0.0f;
    }
    if (tid == 0) g_off[K_] = s_off[K_];

    cudaTriggerProgrammaticLaunchCompletion();
}

// ---------------------------------------------------------------------------
// Kernel 2 (fused): prototypes + inter-class matrix. EXACT R7 inner body
// (200.8us, 64 regs, DRAM 81%): pj[10] register-resident, fully-unrolled
// constant-index loops, pi streamed (register-reused on diagonal tiles),
// __stcs on all output. x (16 MB) + CSR are L2-resident.
//
// New: diag-last block mapping. Diagonal tiles skip the pi recompute ->
// ~15-20% shorter. bids [0, 2880) -> non-diag tiles (chunk fastest, so
// concurrent blocks write contiguous 4KB segments of the same rows);
// bids [2880, 3200) -> the 320 diagonal tiles. The final partial wave
// (240 blocks) is then entirely short tiles, trimming the tail.
// ---------------------------------------------------------------------------
__global__ __launch_bounds__(256, 4) void inter_fused_kernel(
        const float4* __restrict__ x4,
        float4* __restrict__ proto4,
        float4* __restrict__ out4) {
    __shared__ int   s_off[K_ + 1];
    __shared__ int   s_items[B_];
    __shared__ float s_inv[K_];

    // Wait for argmax_csr_kernel's g_* publishes (PDL dependency).
    cudaGridDependencySynchronize();

    const int t = threadIdx.x;
    if (t < K_ + 1) s_off[t]   = g_off[t];
    if (t < B_)     s_items[t] = g_items[t];
    if (t < K_)     s_inv[t]   = g_inv[t];
    __syncthreads();

    // ---- diag-last bid -> (d4 chunk, class tile) mapping ----
    const int bid = blockIdx.x;
    int chunk, i0, j0;
    bool diag;
    if (bid < NNOND_) {
        // non-diagonal tiles first (chunk fastest)
        chunk = bid % NCHUNK_;
        const int q   = bid / NCHUNK_;    // 0..89
        const int r   = q / 9;            // tile row 0..9
        const int c9  = q % 9;            // 0..8
        const int c   = c9 + (c9 >= r ? 1 : 0);   // skip the diagonal column
        i0 = r * TILE_;
        j0 = c * TILE_;
        diag = false;
    } else {
        const int m = bid - NNOND_;       // 0..319
        chunk = m % NCHUNK_;
        const int dq = m / NCHUNK_;       // 0..9
        i0 = dq * TILE_;
        j0 = i0;
        diag = true;
    }
    const int d4 = chunk * 256 + t;       // 0..D4-1

    // prototype rows j0..j0+9 (registers for the whole tile)
    float4 pj[TILE_];
    #pragma unroll
    for (int jj = 0; jj < TILE_; jj++) {
        const int k = j0 + jj;
        float4 acc = make_float4(0.f, 0.f, 0.f, 0.f);
        const int s = s_off[k], e = s_off[k + 1];
        for (int u = s; u < e; u++) {
            float4 v = x4[(size_t)s_items[u] * D4_ + d4];
            acc.x += v.x; acc.y += v.y; acc.z += v.z; acc.w += v.w;
        }
        const float inv = s_inv[k];  // count==0 -> acc==0, inv==0 -> 0 (matches where())
        acc.x *= inv; acc.y *= inv; acc.z *= inv; acc.w *= inv;
        pj[jj] = acc;
    }

    // diagonal tiles publish the prototype output (covers all 100 classes once)
    if (diag) {
        #pragma unroll
        for (int jj = 0; jj < TILE_; jj++)
            __stcs(&proto4[(size_t)(j0 + jj) * D4_ + d4], pj[jj]);
    }

    #pragma unroll
    for (int ii = 0; ii < TILE_; ii++) {
        const int k = i0 + ii;
        float4 pi;
        if (diag) {
            pi = pj[ii];                  // constant index after unroll
        } else {
            float4 acc = make_float4(0.f, 0.f, 0.f, 0.f);
            const int s = s_off[k], e = s_off[k + 1];
            for (int u = s; u < e; u++) {
                float4 v = x4[(size_t)s_items[u] * D4_ + d4];
                acc.x += v.x; acc.y += v.y; acc.z += v.z; acc.w += v.w;
            }
            const float inv = s_inv[k];
            acc.x *= inv; acc.y *= inv; acc.z *= inv; acc.w *= inv;
            pi = acc;
        }
        #pragma unroll
        for (int jj = 0; jj < TILE_; jj++) {
            float4 r;
            r.x = pj[jj].x - pi.x;
            r.y = pj[jj].y - pi.y;
            r.z = pj[jj].z - pi.z;
            r.w = pj[jj].w - pi.w;
            __stcs(&out4[(size_t)(k * K_ + (j0 + jj)) * D4_ + d4], r);
        }
    }
}

// ---------------------------------------------------------------------------
// Launcher. Output layout: [prototypes (100*32768 f32) | inter (100*100*32768 f32)]
// ---------------------------------------------------------------------------
extern "C" void kernel_launch(void* const* d_in, const int* in_sizes, int n_in,
                              void* d_out, int out_size) {
    const float* x      = (const float*)d_in[0];   // (128,128,16,16) f32
    const float* logits = (const float*)d_in[1];   // (128,100) f32
    float* out = (float*)d_out;

    const float4* x4     = (const float4*)x;
    float4*       proto4 = (float4*)out;                       // first 819200 float4
    float4*       inter4 = (float4*)out + (size_t)K_ * D4_;    // rest

    argmax_csr_kernel<<<1, 1024>>>(logits);

    cudaLaunchConfig_t cfg = {};
    cfg.gridDim  = dim3(NNOND_ + NDIAG_);   // 3200 blocks, diag tiles last
    cfg.blockDim = dim3(256);
    cfg.dynamicSmemBytes = 0;
    cfg.stream = 0;
    cudaLaunchAttribute attrs[1];
    attrs[0].id = cudaLaunchAttributeProgrammaticStreamSerialization;
    attrs[0].val.programmaticStreamSerializationAllowed = 1;
    cfg.attrs = attrs;
    cfg.numAttrs = 1;
    cudaLaunchKernelEx(&cfg, inter_fused_kernel, x4, proto4, inter4);
}

// round 13
// speedup vs baseline: 1.1601x; 1.0181x over previous
#include <cuda_runtime.h>

// Problem constants (fixed by the reference: x=(128,128,16,16) f32, logits=(128,100))
#define B_  128
#define D_  32768          // C*H*W
#define D4_ (D_/4)         // 8192 float4 per prototype row
#define K_  100
#define TILE_ 10           // class tile width (j); diag tiles split 5+5 in i
#define NCHUNK_ 32         // d4 chunks of 256
#define NNOND_  (NCHUNK_ * 90)            // 2880 non-diagonal full tiles
#define NDIAGH_ (NCHUNK_ * TILE_ * 2)     // 640 diagonal half tiles
#define NBLOCKS_ (NNOND_ + NDIAGH_)       // 3520

// Scratch (allocation-free rule: __device__ globals)
__device__ int   g_items[B_];    // CSR items: batch indices grouped by class, ascending
__device__ int   g_off[K_ + 1];  // CSR offsets
__device__ float g_inv[K_];      // 1/count (0 if count==0)

// ---------------------------------------------------------------------------
// Kernel 1: argmax per batch row + deterministic CSR build (single block).
// softmax monotone -> argmax(probs) == argmax(logits); strict > + ascending
// scan + (value,index) shuffle reduce matches jnp.argmax tie-breaking.
// ---------------------------------------------------------------------------
__global__ __launch_bounds__(1024) void argmax_csr_kernel(
        const float* __restrict__ logits) {
    __shared__ int s_cls[B_];
    __shared__ int s_cnt[K_];
    __shared__ int s_off[K_ + 1];

    int tid = threadIdx.x;        // 0..1023
    int b   = tid >> 3;           // row 0..127
    int sub = tid & 7;            // 0..7 within row

    if (tid < K_) s_cnt[tid] = 0;

    const float* row = logits + (size_t)b * K_;
    float v   = row[sub];
    int   idx = sub;
    #pragma unroll
    for (int k = sub + 8; k < K_; k += 8) {
        float t = row[k];
        if (t > v) { v = t; idx = k; }   // ascending + strict > => lowest index kept
    }
    #pragma unroll
    for (int off = 4; off > 0; off >>= 1) {
        float ov = __shfl_down_sync(0xffffffffu, v,   off, 8);
        int   oi = __shfl_down_sync(0xffffffffu, idx, off, 8);
        if (ov > v || (ov == v && oi < idx)) { v = ov; idx = oi; }
    }
    __syncthreads();              // counts zeroed before atomics
    if (sub == 0) {
        s_cls[b] = idx;
        atomicAdd(&s_cnt[idx], 1);
    }
    __syncthreads();

    if (tid == 0) {
        int off = 0;
        #pragma unroll 4
        for (int k = 0; k < K_; k++) { s_off[k] = off; off += s_cnt[k]; }
        s_off[K_] = off;
    }
    __syncthreads();

    if (tid < B_) {
        int myc = s_cls[tid];
        int rank = 0;
        #pragma unroll 8
        for (int bb = 0; bb < B_; bb++)
            rank += (bb < tid && s_cls[bb] == myc) ? 1 : 0;
        g_items[s_off[myc] + rank] = tid;
    }

    if (tid < K_) {
        g_off[tid] = s_off[tid];
        int c = s_cnt[tid];
        g_inv[tid] = (c > 0) ? (1.0f / (float)c) : 0.0f;
    }
    if (tid == 0) g_off[K_] = s_off[K_];

    cudaTriggerProgrammaticLaunchCompletion();
}

// ---------------------------------------------------------------------------
// Tile worker: fully specialized at compile time. ILO/ICNT/DIAG are template
// constants -> every pj[] index is a constant after unroll (NO dynamic
// register indexing, the R9/R10 local-spill trap). WRITE_PROTO only on the
// first diag half.
// ---------------------------------------------------------------------------
template <int ILO, int ICNT, bool DIAG>
__device__ __forceinline__ void process_tile(
        int i0, int j0, int d4,
        const int* s_off, const int* s_items, const float* s_inv,
        const float4* __restrict__ x4,
        float4* __restrict__ proto4,
        float4* __restrict__ out4) {
    // prototype rows j0..j0+9 (registers for the whole tile)
    float4 pj[TILE_];
    #pragma unroll
    for (int jj = 0; jj < TILE_; jj++) {
        const int k = j0 + jj;
        float4 acc = make_float4(0.f, 0.f, 0.f, 0.f);
        const int s = s_off[k], e = s_off[k + 1];
        for (int u = s; u < e; u++) {
            float4 v = x4[(size_t)s_items[u] * D4_ + d4];
            acc.x += v.x; acc.y += v.y; acc.z += v.z; acc.w += v.w;
        }
        const float inv = s_inv[k];  // count==0 -> acc==0, inv==0 -> 0 (matches where())
        acc.x *= inv; acc.y *= inv; acc.z *= inv; acc.w *= inv;
        pj[jj] = acc;
    }

    // first diag half publishes the prototype output (once per (row, d4))
    if (DIAG && ILO == 0) {
        #pragma unroll
        for (int jj = 0; jj < TILE_; jj++)
            __stcs(&proto4[(size_t)(j0 + jj) * D4_ + d4], pj[jj]);
    }

    #pragma unroll
    for (int ii = 0; ii < ICNT; ii++) {
        const int k = i0 + ILO + ii;
        float4 pi;
        if (DIAG) {
            pi = pj[ILO + ii];            // compile-time constant index
        } else {
            float4 acc = make_float4(0.f, 0.f, 0.f, 0.f);
            const int s = s_off[k], e = s_off[k + 1];
            for (int u = s; u < e; u++) {
                float4 v = x4[(size_t)s_items[u] * D4_ + d4];
                acc.x += v.x; acc.y += v.y; acc.z += v.z; acc.w += v.w;
            }
            const float inv = s_inv[k];
            acc.x *= inv; acc.y *= inv; acc.z *= inv; acc.w *= inv;
            pi = acc;
        }
        #pragma unroll
        for (int jj = 0; jj < TILE_; jj++) {
            float4 r;
            r.x = pj[jj].x - pi.x;
            r.y = pj[jj].y - pi.y;
            r.z = pj[jj].z - pi.z;
            r.w = pj[jj].w - pi.w;
            __stcs(&out4[(size_t)(k * K_ + (j0 + jj)) * D4_ + d4], r);
        }
    }
}

// ---------------------------------------------------------------------------
// Kernel 2 (fused): prototypes + inter-class matrix.
// 2880 full non-diag tiles (10x10, identical body to the 199.2us best) run
// first; the 320 diagonal tiles run LAST as 640 half tiles (5 i-rows each,
// template-specialized ILO 0/5). The dispatch tail is therefore made of
// ~half-duration blocks: elapsed ~= ideal(181us) + t_diag/2 instead of
// + t_diag. x (16 MB) + CSR are L2-resident; writes are the only DRAM
// traffic, pinned at the ~6.44 TB/s write ceiling.
// ---------------------------------------------------------------------------
__global__ __launch_bounds__(256, 4) void inter_fused_kernel(
        const float4* __restrict__ x4,
        float4* __restrict__ proto4,
        float4* __restrict__ out4) {
    __shared__ int   s_off[K_ + 1];
    __shared__ int   s_items[B_];
    __shared__ float s_inv[K_];

    // Wait for argmax_csr_kernel's g_* publishes (PDL dependency).
    cudaGridDependencySynchronize();

    const int t = threadIdx.x;
    if (t < K_ + 1) s_off[t]   = g_off[t];
    if (t < B_)     s_items[t] = g_items[t];
    if (t < K_)     s_inv[t]   = g_inv[t];
    __syncthreads();

    const int bid = blockIdx.x;
    if (bid < NNOND_) {
        // non-diagonal full tiles (chunk fastest)
        const int chunk = bid % NCHUNK_;
        const int q   = bid / NCHUNK_;    // 0..89
        const int r   = q / 9;            // tile row 0..9
        const int c9  = q % 9;
        const int c   = c9 + (c9 >= r ? 1 : 0);   // skip diagonal column
        process_tile<0, TILE_, false>(r * TILE_, c * TILE_, chunk * 256 + t,
                                      s_off, s_items, s_inv, x4, proto4, out4);
    } else {
        // diagonal half tiles, dispatched last
        const int m     = bid - NNOND_;   // 0..639
        const int chunk = m % NCHUNK_;
        const int q     = m / NCHUNK_;    // 0..19
        const int dq    = q >> 1;         // diag tile 0..9
        const int i0    = dq * TILE_;
        const int d4    = chunk * 256 + t;
        if ((q & 1) == 0)
            process_tile<0, TILE_ / 2, true>(i0, i0, d4, s_off, s_items, s_inv,
                                             x4, proto4, out4);
        else
            process_tile<TILE_ / 2, TILE_ / 2, true>(i0, i0, d4, s_off, s_items,
                                                     s_inv, x4, proto4, out4);
    }
}

// ---------------------------------------------------------------------------
// Launcher. Output layout: [prototypes (100*32768 f32) | inter (100*100*32768 f32)]
// ---------------------------------------------------------------------------
extern "C" void kernel_launch(void* const* d_in, const int* in_sizes, int n_in,
                              void* d_out, int out_size) {
    const float* x      = (const float*)d_in[0];   // (128,128,16,16) f32
    const float* logits = (const float*)d_in[1];   // (128,100) f32
    float* out = (float*)d_out;

    const float4* x4     = (const float4*)x;
    float4*       proto4 = (float4*)out;                       // first 819200 float4
    float4*       inter4 = (float4*)out + (size_t)K_ * D4_;    // rest

    argmax_csr_kernel<<<1, 1024>>>(logits);

    cudaLaunchConfig_t cfg = {};
    cfg.gridDim  = dim3(NBLOCKS_);   // 3520: 2880 full non-diag + 640 diag halves
    cfg.blockDim = dim3(256);
    cfg.dynamicSmemBytes = 0;
    cfg.stream = 0;
    cudaLaunchAttribute attrs[1];
    attrs[0].id = cudaLaunchAttributeProgrammaticStreamSerialization;
    attrs[0].val.programmaticStreamSerializationAllowed = 1;
    cfg.attrs = attrs;
    cfg.numAttrs = 1;
    cudaLaunchKernelEx(&cfg, inter_fused_kernel, x4, proto4, inter4);
}